// round 5
// baseline (speedup 1.0000x reference)
#include <cuda_runtime.h>
#include <math.h>

#define NN 100000
#define NE 1600000
#define SD 64
#define VD 64
#define HID 128
#define INP 196           // 195 real + 1 zero-padded row
#define TILE 64
#define STRA 68           // A/H row stride (floats); 272B, 16B-aligned
#define NT ((NE + TILE - 1) / TILE)
#define NTHREADS 256

// dynamic smem (floats): W1s INP*HID + W2s HID*HID + A INP*STRA (+64 ints)
#define SMEM_FLOATS (INP*HID + HID*HID + INP*STRA)
#define SMEM_BYTES  (SMEM_FLOATS*4 + TILE*4)

typedef unsigned long long u64;

#define FMA2(d, a, b) \
    asm("fma.rn.f32x2 %0, %1, %2, %0;" : "+l"(d) : "l"(a), "l"(b))
#define PACK2(d, f) \
    asm("mov.b64 %0, {%1, %1};" : "=l"(d) : "f"(f))
#define UNPACK2(lo, hi, v) \
    asm("mov.b64 {%0, %1}, %2;" : "=f"(lo), "=f"(hi) : "l"(v))

__device__ __forceinline__ void red_add_v4(float* a, float x, float y, float z, float w) {
    asm volatile("red.global.add.v4.f32 [%0], {%1,%2,%3,%4};"
                 :: "l"(a), "f"(x), "f"(y), "f"(z), "f"(w) : "memory");
}

__device__ __forceinline__ float silu(float x) {
    return x * (1.f / (1.f + __expf(-x)));
}

__global__ void init_out_kernel(const float* __restrict__ hs,
                                const float* __restrict__ hv,
                                float* __restrict__ out) {
    size_t i = (size_t)blockIdx.x * blockDim.x + threadIdx.x;
    const size_t n4 = (size_t)NN * SD / 4;
    const float4* hs4 = (const float4*)hs;
    const float4* hv4 = (const float4*)hv;
    float4* o4 = (float4*)out;
    if (i < n4) {
        o4[i]      = hs4[i];
        o4[n4 + i] = hv4[i];
    }
}

extern __shared__ float sm[];

__global__ void __launch_bounds__(NTHREADS, 1)
edge_kernel(const float* __restrict__ h_s, const float* __restrict__ h_v,
            const float* __restrict__ pos, const float* __restrict__ orient,
            const float* __restrict__ W1,  const float* __restrict__ b1,
            const float* __restrict__ W2,  const float* __restrict__ b2,
            const int*   __restrict__ ei,  float* __restrict__ out) {
    float* W1s = sm;                       // [INP][HID]
    float* W2s = sm + INP * HID;           // [HID][HID]
    float* A   = W2s + HID * HID;          // [INP][STRA], reused as H[HID][STRA]
    int*  dstS = (int*)(A + INP * STRA);   // [TILE]

    const int tid = threadIdx.x;
    const int tx = tid & 15;               // output group: outs tx*4..+3 and 64+tx*4..+3
    const int ty = tid >> 4;               // edge group (0..15): edges ty*4..ty*4+3

    // ---- load weights into SMEM once (persistent blocks) ----
    {
        const float4* g1 = (const float4*)W1;
        float4* s1 = (float4*)W1s;
        for (int i = tid; i < (195 * HID) / 4; i += NTHREADS) s1[i] = g1[i];
        float4 z4 = make_float4(0.f, 0.f, 0.f, 0.f);
        for (int i = tid; i < HID / 4; i += NTHREADS)
            ((float4*)(W1s + 195 * HID))[i] = z4;       // padded row 195 = 0
        const float4* g2 = (const float4*)W2;
        float4* s2 = (float4*)W2s;
        for (int i = tid; i < (HID * HID) / 4; i += NTHREADS) s2[i] = g2[i];
    }

    // bias pairs, loaded directly as 8B words (lanes = adjacent outputs)
    u64 b1p[4], b2p[4];
    b1p[0] = *(const u64*)(b1 + tx * 4);
    b1p[1] = *(const u64*)(b1 + tx * 4 + 2);
    b1p[2] = *(const u64*)(b1 + 64 + tx * 4);
    b1p[3] = *(const u64*)(b1 + 64 + tx * 4 + 2);
    b2p[0] = *(const u64*)(b2 + tx * 4);
    b2p[1] = *(const u64*)(b2 + tx * 4 + 2);
    b2p[2] = *(const u64*)(b2 + 64 + tx * 4);
    b2p[3] = *(const u64*)(b2 + 64 + tx * 4 + 2);

    const int e = tid & 63;                // builder edge (0..63)
    const int p = tid >> 6;                // builder role (0..3) — warp-uniform

    const float* Acol  = A + ty * 4;
    const float* Wcol1 = W1s + tx * 4;     // conflict-free 256B contiguous per 16 lanes
    const float* Wcol2 = W2s + tx * 4;

    for (int tile = blockIdx.x; tile < NT; tile += gridDim.x) {
        __syncthreads();   // protect A/H + dstS reuse across tiles

        // ---- build message-input tile A[196][64] (4 threads per edge) ----
        {
            int ge = tile * TILE + e;
            bool valid = ge < NE;
            int src = valid ? ei[ge] : 0;
            int dst = valid ? ei[NE + ge] : 0;
            if (p == 0) {                  // rows 0..63: h_s[src]
                const float4* r = (const float4*)(h_s + (size_t)src * SD);
                #pragma unroll
                for (int j = 0; j < 16; j++) {
                    float4 v = r[j];
                    A[(4*j+0)*STRA + e] = v.x;
                    A[(4*j+1)*STRA + e] = v.y;
                    A[(4*j+2)*STRA + e] = v.z;
                    A[(4*j+3)*STRA + e] = v.w;
                }
            } else if (p == 1) {           // rows 64..127: h_s[dst]
                const float4* r = (const float4*)(h_s + (size_t)dst * SD);
                #pragma unroll
                for (int j = 0; j < 16; j++) {
                    float4 v = r[j];
                    A[(64+4*j+0)*STRA + e] = v.x;
                    A[(64+4*j+1)*STRA + e] = v.y;
                    A[(64+4*j+2)*STRA + e] = v.z;
                    A[(64+4*j+3)*STRA + e] = v.w;
                }
            } else if (p == 2) {           // rows 128..191: rotated h_v[src]
                float alpha = orient[dst];
                float beta  = orient[src];
                float c, s_;
                sincosf(2.f * (beta - alpha), &s_, &c);
                const float4* r = (const float4*)(h_v + (size_t)src * VD);
                #pragma unroll
                for (int j = 0; j < 16; j++) {
                    float4 v = r[j];
                    A[(128+4*j+0)*STRA + e] = v.x * c - v.y * s_;
                    A[(128+4*j+1)*STRA + e] = v.x * s_ + v.y * c;
                    A[(128+4*j+2)*STRA + e] = v.z * c - v.w * s_;
                    A[(128+4*j+3)*STRA + e] = v.z * s_ + v.w * c;
                }
            } else {                       // rows 192..195: geo features + pad
                float2 ps = ((const float2*)pos)[src];
                float2 pd = ((const float2*)pos)[dst];
                float dx = ps.x - pd.x, dy = ps.y - pd.y;
                float dist = sqrtf(dx * dx + dy * dy) + 1e-6f;
                float alpha = orient[dst];
                float dphi = atan2f(dy, dx) - alpha;
                float c2, s2;
                sincosf(2.f * dphi, &s2, &c2);
                A[192*STRA + e] = dist;
                A[193*STRA + e] = c2;
                A[194*STRA + e] = s2;
                A[195*STRA + e] = 0.f;
                dstS[e] = valid ? dst : -1;
            }
        }
        __syncthreads();

        // ---- layer 1: lanes = output pairs; W pairs come straight from LDS ----
        u64 acc[4][4];                     // [edge][output pair]
        #pragma unroll
        for (int i = 0; i < 4; i++)
            #pragma unroll
            for (int q = 0; q < 4; q++) acc[i][q] = b1p[q];

        #pragma unroll 2
        for (int k = 0; k < INP; k++) {
            float4 a4 = *(const float4*)(Acol + k * STRA);             // 4 edges (broadcast)
            ulonglong2 w0 = *(const ulonglong2*)(Wcol1 + k * HID);     // outs tx*4..+3 (2 pairs)
            ulonglong2 w1 = *(const ulonglong2*)(Wcol1 + k * HID + 64);// outs 64+tx*4..+3
            u64 ad[4];
            PACK2(ad[0], a4.x); PACK2(ad[1], a4.y);
            PACK2(ad[2], a4.z); PACK2(ad[3], a4.w);
            u64 wp[4] = {w0.x, w0.y, w1.x, w1.y};
            #pragma unroll
            for (int i = 0; i < 4; i++)
                #pragma unroll
                for (int q = 0; q < 4; q++)
                    FMA2(acc[i][q], ad[i], wp[q]);
        }
        __syncthreads();   // all reads of A done before H overwrites it

        // ---- SiLU + store H[out][edge] into A's buffer ----
        {
            float h[4][8];   // [edge][out j] ; j<4 -> tx*4+j , j>=4 -> 64+tx*4+(j-4)
            #pragma unroll
            for (int i = 0; i < 4; i++) {
                #pragma unroll
                for (int q = 0; q < 4; q++) {
                    float lo, hi;
                    UNPACK2(lo, hi, acc[i][q]);
                    h[i][2*q]   = silu(lo);
                    h[i][2*q+1] = silu(hi);
                }
            }
            #pragma unroll
            for (int j = 0; j < 8; j++) {
                int o = (j < 4) ? (tx * 4 + j) : (64 + tx * 4 + (j - 4));
                *(float4*)(A + o * STRA + ty * 4) =
                    make_float4(h[0][j], h[1][j], h[2][j], h[3][j]);
            }
        }
        __syncthreads();

        // ---- layer 2 ----
        u64 acc2[4][4];
        #pragma unroll
        for (int i = 0; i < 4; i++)
            #pragma unroll
            for (int q = 0; q < 4; q++) acc2[i][q] = b2p[q];

        #pragma unroll 2
        for (int k = 0; k < HID; k++) {
            float4 a4 = *(const float4*)(Acol + k * STRA);
            ulonglong2 w0 = *(const ulonglong2*)(Wcol2 + k * HID);
            ulonglong2 w1 = *(const ulonglong2*)(Wcol2 + k * HID + 64);
            u64 ad[4];
            PACK2(ad[0], a4.x); PACK2(ad[1], a4.y);
            PACK2(ad[2], a4.z); PACK2(ad[3], a4.w);
            u64 wp[4] = {w0.x, w0.y, w1.x, w1.y};
            #pragma unroll
            for (int i = 0; i < 4; i++)
                #pragma unroll
                for (int q = 0; q < 4; q++)
                    FMA2(acc2[i][q], ad[i], wp[q]);
        }

        // ---- scatter-add: pairs q<2 -> msg_s cols tx*4..+3 ; q>=2 -> msg_v ----
        const size_t outv_off = (size_t)NN * SD;
        #pragma unroll
        for (int i = 0; i < 4; i++) {
            int d = dstS[ty * 4 + i];
            float m0, m1, m2, m3, m4, m5, m6, m7;
            UNPACK2(m0, m1, acc2[i][0]);
            UNPACK2(m2, m3, acc2[i][1]);
            UNPACK2(m4, m5, acc2[i][2]);
            UNPACK2(m6, m7, acc2[i][3]);
            if (d >= 0) {
                red_add_v4(out + (size_t)d * SD + tx * 4, m0, m1, m2, m3);
                red_add_v4(out + outv_off + (size_t)d * VD + tx * 4, m4, m5, m6, m7);
            }
        }
    }
}

extern "C" void kernel_launch(void* const* d_in, const int* in_sizes, int n_in,
                              void* d_out, int out_size) {
    const float* h_s    = (const float*)d_in[0];
    const float* h_v    = (const float*)d_in[1];
    const float* pos    = (const float*)d_in[2];
    const float* orient = (const float*)d_in[3];
    const float* W1     = (const float*)d_in[4];
    const float* b1     = (const float*)d_in[5];
    const float* W2     = (const float*)d_in[6];
    const float* b2     = (const float*)d_in[7];
    const int*   ei     = (const int*)d_in[8];
    float* out = (float*)d_out;

    (void)in_sizes; (void)n_in; (void)out_size;

    int n4 = NN * SD / 4;
    init_out_kernel<<<(n4 + 255) / 256, 256>>>(h_s, h_v, out);

    cudaFuncSetAttribute(edge_kernel,
                         cudaFuncAttributeMaxDynamicSharedMemorySize, SMEM_BYTES);
    int nsm = 148;
    cudaDeviceGetAttribute(&nsm, cudaDevAttrMultiProcessorCount, 0);
    edge_kernel<<<nsm, NTHREADS, SMEM_BYTES>>>(h_s, h_v, pos, orient,
                                               W1, b1, W2, b2, ei, out);
}

// round 9
// speedup vs baseline: 1.7730x; 1.7730x over previous
#include <cuda_runtime.h>
#include <math.h>

#define NN 100000
#define NE 1600000
#define SD 64
#define VD 64
#define HID 128
#define INP 196           // 195 real + 1 zero-padded row
#define TILE 64
#define STRA 68           // A/H row stride (floats); 272B, 16B-aligned
#define NT ((NE + TILE - 1) / TILE)
#define NTHREADS 256

// dynamic smem (floats): W1s INP*HID + W2s HID*HID + A INP*STRA (+64 ints)
#define SMEM_FLOATS (INP*HID + HID*HID + INP*STRA)
#define SMEM_BYTES  (SMEM_FLOATS*4 + TILE*4)

typedef unsigned long long u64;

#define FMA2(d, a, b) \
    asm("fma.rn.f32x2 %0, %1, %2, %0;" : "+l"(d) : "l"(a), "l"(b))
#define PACK2(d, f) \
    asm("mov.b64 %0, {%1, %1};" : "=l"(d) : "f"(f))
#define UNPACK2(lo, hi, v) \
    asm("mov.b64 {%0, %1}, %2;" : "=f"(lo), "=f"(hi) : "l"(v))

__device__ __forceinline__ void red_add_v4(float* a, float x, float y, float z, float w) {
    asm volatile("red.global.add.v4.f32 [%0], {%1,%2,%3,%4};"
                 :: "l"(a), "f"(x), "f"(y), "f"(z), "f"(w) : "memory");
}

__device__ __forceinline__ float silu(float x) {
    return x * (1.f / (1.f + __expf(-x)));
}

__global__ void init_out_kernel(const float* __restrict__ hs,
                                const float* __restrict__ hv,
                                float* __restrict__ out) {
    size_t i = (size_t)blockIdx.x * blockDim.x + threadIdx.x;
    const size_t n4 = (size_t)NN * SD / 4;
    const float4* hs4 = (const float4*)hs;
    const float4* hv4 = (const float4*)hv;
    float4* o4 = (float4*)out;
    if (i < n4) {
        o4[i]      = hs4[i];
        o4[n4 + i] = hv4[i];
    }
}

extern __shared__ float sm[];

__global__ void __launch_bounds__(NTHREADS, 1)
edge_kernel(const float* __restrict__ h_s, const float* __restrict__ h_v,
            const float* __restrict__ pos, const float* __restrict__ orient,
            const float* __restrict__ W1,  const float* __restrict__ b1,
            const float* __restrict__ W2,  const float* __restrict__ b2,
            const int*   __restrict__ ei,  float* __restrict__ out) {
    float* W1s = sm;                       // [INP][HID]
    float* W2s = sm + INP * HID;           // [HID][HID]
    float* A   = W2s + HID * HID;          // [INP][STRA], reused as H[HID][STRA]
    int*  dstS = (int*)(A + INP * STRA);   // [TILE]

    const int tid = threadIdx.x;
    const int tx = tid & 31;               // output group: outs tx*4 .. tx*4+3
    const int ty = tid >> 5;               // warp id (0..7): edges ty*8 .. ty*8+7 (warp-uniform)

    // ---- load weights into SMEM once (persistent blocks) ----
    {
        const float4* g1 = (const float4*)W1;
        float4* s1 = (float4*)W1s;
        for (int i = tid; i < (195 * HID) / 4; i += NTHREADS) s1[i] = g1[i];
        float4 z4 = make_float4(0.f, 0.f, 0.f, 0.f);
        for (int i = tid; i < HID / 4; i += NTHREADS)
            ((float4*)(W1s + 195 * HID))[i] = z4;       // padded row 195 = 0
        const float4* g2 = (const float4*)W2;
        float4* s2 = (float4*)W2s;
        for (int i = tid; i < (HID * HID) / 4; i += NTHREADS) s2[i] = g2[i];
    }

    // bias pairs for this thread's 4 outputs (lanes = edge pairs -> duplicate bias)
    u64 b1p[4], b2p[4];
    #pragma unroll
    for (int j = 0; j < 4; j++) {
        float v1 = b1[tx * 4 + j], v2 = b2[tx * 4 + j];
        PACK2(b1p[j], v1);
        PACK2(b2p[j], v2);
    }

    const int e = tid & 63;                // builder edge (0..63)
    const int p = tid >> 6;                // builder role (0..3) — warp-uniform

    const float* Acol  = A + ty * 8;
    const float* Wcol1 = W1s + tx * 4;     // contiguous 512B per warp, conflict-free
    const float* Wcol2 = W2s + tx * 4;

    for (int tile = blockIdx.x; tile < NT; tile += gridDim.x) {
        __syncthreads();   // protect A/H + dstS reuse across tiles

        // ---- build message-input tile A[196][64] (4 threads per edge) ----
        {
            int ge = tile * TILE + e;
            bool valid = ge < NE;
            int src = valid ? ei[ge] : 0;
            int dst = valid ? ei[NE + ge] : 0;
            if (p == 0) {                  // rows 0..63: h_s[src]
                const float4* r = (const float4*)(h_s + (size_t)src * SD);
                #pragma unroll
                for (int j = 0; j < 16; j++) {
                    float4 v = r[j];
                    A[(4*j+0)*STRA + e] = v.x;
                    A[(4*j+1)*STRA + e] = v.y;
                    A[(4*j+2)*STRA + e] = v.z;
                    A[(4*j+3)*STRA + e] = v.w;
                }
            } else if (p == 1) {           // rows 64..127: h_s[dst]
                const float4* r = (const float4*)(h_s + (size_t)dst * SD);
                #pragma unroll
                for (int j = 0; j < 16; j++) {
                    float4 v = r[j];
                    A[(64+4*j+0)*STRA + e] = v.x;
                    A[(64+4*j+1)*STRA + e] = v.y;
                    A[(64+4*j+2)*STRA + e] = v.z;
                    A[(64+4*j+3)*STRA + e] = v.w;
                }
            } else if (p == 2) {           // rows 128..191: rotated h_v[src]
                float alpha = orient[dst];
                float beta  = orient[src];
                float c, s_;
                sincosf(2.f * (beta - alpha), &s_, &c);
                const float4* r = (const float4*)(h_v + (size_t)src * VD);
                #pragma unroll
                for (int j = 0; j < 16; j++) {
                    float4 v = r[j];
                    A[(128+4*j+0)*STRA + e] = v.x * c - v.y * s_;
                    A[(128+4*j+1)*STRA + e] = v.x * s_ + v.y * c;
                    A[(128+4*j+2)*STRA + e] = v.z * c - v.w * s_;
                    A[(128+4*j+3)*STRA + e] = v.z * s_ + v.w * c;
                }
            } else {                       // rows 192..195: geo features + pad
                float2 ps = ((const float2*)pos)[src];
                float2 pd = ((const float2*)pos)[dst];
                float dx = ps.x - pd.x, dy = ps.y - pd.y;
                float dist = sqrtf(dx * dx + dy * dy) + 1e-6f;
                float alpha = orient[dst];
                float dphi = atan2f(dy, dx) - alpha;
                float c2, s2;
                sincosf(2.f * dphi, &s2, &c2);
                A[192*STRA + e] = dist;
                A[193*STRA + e] = c2;
                A[194*STRA + e] = s2;
                A[195*STRA + e] = 0.f;
                dstS[e] = valid ? dst : -1;
            }
        }
        __syncthreads();

        // ---- layer 1: lanes = edge pairs (A direct from LDS), W packed ----
        u64 acc[4][4];                     // [edge pair][output j]
        #pragma unroll
        for (int i = 0; i < 4; i++)
            #pragma unroll
            for (int j = 0; j < 4; j++) acc[i][j] = b1p[j];

        #pragma unroll 2
        for (int k = 0; k < INP; k++) {
            ulonglong2 a01 = *(const ulonglong2*)(Acol + k * STRA);      // edges +0..3 (bcast)
            ulonglong2 a23 = *(const ulonglong2*)(Acol + k * STRA + 4);  // edges +4..7
            float4 w = *(const float4*)(Wcol1 + k * HID);                // 4 outputs
            u64 av[4] = {a01.x, a01.y, a23.x, a23.y};
            u64 wd[4];
            PACK2(wd[0], w.x); PACK2(wd[1], w.y);
            PACK2(wd[2], w.z); PACK2(wd[3], w.w);
            #pragma unroll
            for (int i = 0; i < 4; i++)
                #pragma unroll
                for (int j = 0; j < 4; j++)
                    FMA2(acc[i][j], av[i], wd[j]);
        }
        __syncthreads();   // all reads of A done before H overwrites it

        // ---- SiLU + store H[out][edge] into A's buffer ----
        #pragma unroll
        for (int j = 0; j < 4; j++) {
            int o = tx * 4 + j;
            float h[8];
            #pragma unroll
            for (int i = 0; i < 4; i++) {
                float lo, hi;
                UNPACK2(lo, hi, acc[i][j]);
                h[2*i]   = silu(lo);
                h[2*i+1] = silu(hi);
            }
            *(float4*)(A + o * STRA + ty * 8)     = make_float4(h[0], h[1], h[2], h[3]);
            *(float4*)(A + o * STRA + ty * 8 + 4) = make_float4(h[4], h[5], h[6], h[7]);
        }
        __syncthreads();

        // ---- layer 2 ----
        u64 acc2[4][4];
        #pragma unroll
        for (int i = 0; i < 4; i++)
            #pragma unroll
            for (int j = 0; j < 4; j++) acc2[i][j] = b2p[j];

        #pragma unroll 2
        for (int k = 0; k < HID; k++) {
            ulonglong2 a01 = *(const ulonglong2*)(Acol + k * STRA);
            ulonglong2 a23 = *(const ulonglong2*)(Acol + k * STRA + 4);
            float4 w = *(const float4*)(Wcol2 + k * HID);
            u64 av[4] = {a01.x, a01.y, a23.x, a23.y};
            u64 wd[4];
            PACK2(wd[0], w.x); PACK2(wd[1], w.y);
            PACK2(wd[2], w.z); PACK2(wd[3], w.w);
            #pragma unroll
            for (int i = 0; i < 4; i++)
                #pragma unroll
                for (int j = 0; j < 4; j++)
                    FMA2(acc2[i][j], av[i], wd[j]);
        }

        // ---- scatter-add: this thread owns cols tx*4..+3 for 8 edges ----
        // tx<16 -> msg_s (cols tx*4), tx>=16 -> msg_v (cols (tx-16)*4)
        const size_t outv_off = (size_t)NN * SD;
        #pragma unroll
        for (int i = 0; i < 4; i++) {
            float m0, m1, m2, m3, n0, n1, n2, n3;
            UNPACK2(m0, n0, acc2[i][0]);
            UNPACK2(m1, n1, acc2[i][1]);
            UNPACK2(m2, n2, acc2[i][2]);
            UNPACK2(m3, n3, acc2[i][3]);
            int e0 = ty * 8 + 2 * i;
            int d0 = dstS[e0];
            int d1 = dstS[e0 + 1];
            if (d0 >= 0) {
                float* b = (tx < 16)
                    ? out + (size_t)d0 * SD + tx * 4
                    : out + outv_off + (size_t)d0 * VD + (tx - 16) * 4;
                red_add_v4(b, m0, m1, m2, m3);
            }
            if (d1 >= 0) {
                float* b = (tx < 16)
                    ? out + (size_t)d1 * SD + tx * 4
                    : out + outv_off + (size_t)d1 * VD + (tx - 16) * 4;
                red_add_v4(b, n0, n1, n2, n3);
            }
        }
    }
}

extern "C" void kernel_launch(void* const* d_in, const int* in_sizes, int n_in,
                              void* d_out, int out_size) {
    const float* h_s    = (const float*)d_in[0];
    const float* h_v    = (const float*)d_in[1];
    const float* pos    = (const float*)d_in[2];
    const float* orient = (const float*)d_in[3];
    const float* W1     = (const float*)d_in[4];
    const float* b1     = (const float*)d_in[5];
    const float* W2     = (const float*)d_in[6];
    const float* b2     = (const float*)d_in[7];
    const int*   ei     = (const int*)d_in[8];
    float* out = (float*)d_out;

    (void)in_sizes; (void)n_in; (void)out_size;

    int n4 = NN * SD / 4;
    init_out_kernel<<<(n4 + 255) / 256, 256>>>(h_s, h_v, out);

    cudaFuncSetAttribute(edge_kernel,
                         cudaFuncAttributeMaxDynamicSharedMemorySize, SMEM_BYTES);
    int nsm = 148;
    cudaDeviceGetAttribute(&nsm, cudaDevAttrMultiProcessorCount, 0);
    edge_kernel<<<nsm, NTHREADS, SMEM_BYTES>>>(h_s, h_v, pos, orient,
                                               W1, b1, W2, b2, ei, out);
}

// round 13
// speedup vs baseline: 1.8805x; 1.0606x over previous
#include <cuda_runtime.h>
#include <math.h>
#include <stdint.h>

#define NN 100000
#define NE 1600000
#define SD 64
#define VD 64
#define HID 128
#define TILE 64
#define NT (NE / TILE)            // 25000 exact
#define NTHREADS 256

// SMEM layout (bytes)
#define W1K 200                   // layer1 K padded to 25 k-steps of 8
#define W2K 128
#define WST 132                   // weight row stride [k][m] — conflict-free A-frags
#define BST 68                    // message row stride [k][e] — conflict-free B-frags
#define W1S_OFF 0
#define W2S_OFF (W1K * WST * 4)               // 105600
#define B1_OFF  (W2S_OFF + W2K * WST * 4)     // 173184  (H aliases this)
#define DST_OFF (B1_OFF + W1K * BST * 4)      // 227584
#define SMEM_BYTES (DST_OFF + 256)            // 227840 < 232448 limit

__device__ __forceinline__ uint32_t tf32u(float x) {
    uint32_t u;
    asm("cvt.rna.tf32.f32 %0, %1;" : "=r"(u) : "f"(x));
    return u;
}

__device__ __forceinline__ void mma8(float c[4], uint32_t a0, uint32_t a1,
                                     uint32_t a2, uint32_t a3,
                                     uint32_t b0, uint32_t b1) {
    asm volatile("mma.sync.aligned.m16n8k8.row.col.f32.tf32.tf32.f32 "
        "{%0,%1,%2,%3}, {%4,%5,%6,%7}, {%8,%9}, {%0,%1,%2,%3};"
        : "+f"(c[0]), "+f"(c[1]), "+f"(c[2]), "+f"(c[3])
        : "r"(a0), "r"(a1), "r"(a2), "r"(a3), "r"(b0), "r"(b1));
}

__device__ __forceinline__ void red_add_f(float* a, float v) {
    asm volatile("red.global.add.f32 [%0], %1;" :: "l"(a), "f"(v) : "memory");
}

__device__ __forceinline__ float silu(float x) {
    return x * (1.f / (1.f + __expf(-x)));
}

__global__ void init_out_kernel(const float* __restrict__ hs,
                                const float* __restrict__ hv,
                                float* __restrict__ out) {
    size_t i = (size_t)blockIdx.x * blockDim.x + threadIdx.x;
    const size_t n4 = (size_t)NN * SD / 4;
    if (i < n4) {
        ((float4*)out)[i]      = ((const float4*)hs)[i];
        ((float4*)out)[n4 + i] = ((const float4*)hv)[i];
    }
}

extern __shared__ float sm[];

__global__ void __launch_bounds__(NTHREADS, 1)
edge_kernel(const float* __restrict__ h_s, const float* __restrict__ h_v,
            const float* __restrict__ pos, const float* __restrict__ orient,
            const float* __restrict__ W1,  const float* __restrict__ gb1,
            const float* __restrict__ W2,  const float* __restrict__ gb2,
            const int*   __restrict__ ei,  float* __restrict__ out) {
    float* W1s = sm;                           // [W1K][WST]
    float* W2s = (float*)((char*)sm + W2S_OFF);// [W2K][WST]
    float* B1  = (float*)((char*)sm + B1_OFF); // [W1K][BST]; H aliases [128][BST]
    int*  dstS = (int*)((char*)sm + DST_OFF);  // [TILE]

    const int tid  = threadIdx.x;
    const int wid  = tid >> 5;
    const int lane = tid & 31;
    const int qa   = lane & 3;                 // threadID_in_group
    const int ra   = lane >> 2;                // groupID
    const int m0   = wid * 16;                 // this warp's output-row base

    // ---- load weights (tf32-rounded) into SMEM, [k][m] stride WST ----
    for (int idx = tid; idx < W1K * HID; idx += NTHREADS) {
        int k = idx >> 7, m = idx & 127;
        float v = (k < 196) ? W1[(size_t)k * HID + m] : 0.f;
        W1s[k * WST + m] = __uint_as_float(tf32u(v));
    }
    for (int idx = tid; idx < W2K * HID; idx += NTHREADS) {
        int k = idx >> 7, m = idx & 127;
        W2s[k * WST + m] = __uint_as_float(tf32u(W2[(size_t)k * HID + m]));
    }

    // biases for this thread's c-frag rows (rows m0+ra and m0+ra+8)
    const float b1lo = gb1[m0 + ra],     b1hi = gb1[m0 + ra + 8];
    const float b2lo = gb2[m0 + ra],     b2hi = gb2[m0 + ra + 8];

    const int e = tid & 63;                    // builder edge
    const int p = tid >> 6;                    // builder role (warp-uniform)
    const size_t outv_off = (size_t)NN * SD;
    // epilogue-2 base: warps 0-3 -> msg_s rows, warps 4-7 -> msg_v rows
    float* obase = (m0 < 64) ? out : out + outv_off;
    const int rlo = (m0 < 64) ? (m0 + ra) : (m0 - 64 + ra);

    for (int tile = blockIdx.x; tile < NT; tile += gridDim.x) {
        __syncthreads();   // B1/H + dstS safe to overwrite

        // ---- build message tile B1[k][e], tf32-rounded, stride BST ----
        {
            int ge = tile * TILE + e;
            int src = ei[ge];
            int dst = ei[NE + ge];
            if (p == 0) {                      // k 0..63 : h_s[src]
                const float4* r = (const float4*)(h_s + (size_t)src * SD);
                #pragma unroll
                for (int j = 0; j < 16; j++) {
                    float4 v = r[j];
                    B1[(4*j+0)*BST + e] = __uint_as_float(tf32u(v.x));
                    B1[(4*j+1)*BST + e] = __uint_as_float(tf32u(v.y));
                    B1[(4*j+2)*BST + e] = __uint_as_float(tf32u(v.z));
                    B1[(4*j+3)*BST + e] = __uint_as_float(tf32u(v.w));
                }
            } else if (p == 1) {               // k 64..127 : h_s[dst]
                const float4* r = (const float4*)(h_s + (size_t)dst * SD);
                #pragma unroll
                for (int j = 0; j < 16; j++) {
                    float4 v = r[j];
                    B1[(64+4*j+0)*BST + e] = __uint_as_float(tf32u(v.x));
                    B1[(64+4*j+1)*BST + e] = __uint_as_float(tf32u(v.y));
                    B1[(64+4*j+2)*BST + e] = __uint_as_float(tf32u(v.z));
                    B1[(64+4*j+3)*BST + e] = __uint_as_float(tf32u(v.w));
                }
            } else if (p == 2) {               // k 128..191 : rotated h_v[src]
                float alpha = orient[dst];
                float beta  = orient[src];
                float c, s_;
                sincosf(2.f * (beta - alpha), &s_, &c);
                const float4* r = (const float4*)(h_v + (size_t)src * VD);
                #pragma unroll
                for (int j = 0; j < 16; j++) {
                    float4 v = r[j];
                    B1[(128+4*j+0)*BST + e] = __uint_as_float(tf32u(v.x * c - v.y * s_));
                    B1[(128+4*j+1)*BST + e] = __uint_as_float(tf32u(v.x * s_ + v.y * c));
                    B1[(128+4*j+2)*BST + e] = __uint_as_float(tf32u(v.z * c - v.w * s_));
                    B1[(128+4*j+3)*BST + e] = __uint_as_float(tf32u(v.z * s_ + v.w * c));
                }
            } else {                           // k 192..199 : geo + zero pad
                float2 ps = ((const float2*)pos)[src];
                float2 pd = ((const float2*)pos)[dst];
                float dx = ps.x - pd.x, dy = ps.y - pd.y;
                float dist = sqrtf(dx * dx + dy * dy) + 1e-6f;
                float alpha = orient[dst];
                float dphi = atan2f(dy, dx) - alpha;
                float c2, s2;
                sincosf(2.f * dphi, &s2, &c2);
                B1[192*BST + e] = __uint_as_float(tf32u(dist));
                B1[193*BST + e] = __uint_as_float(tf32u(c2));
                B1[194*BST + e] = __uint_as_float(tf32u(s2));
                B1[195*BST + e] = 0.f;
                B1[196*BST + e] = 0.f;
                B1[197*BST + e] = 0.f;
                B1[198*BST + e] = 0.f;
                B1[199*BST + e] = 0.f;
                dstS[e] = dst;
            }
        }
        __syncthreads();

        // ---- layer 1: D1[m16][n64] = W1^T x B1, K=200 (25 k-steps) ----
        float c1[8][4];
        #pragma unroll
        for (int t = 0; t < 8; t++) {
            c1[t][0] = b1lo; c1[t][1] = b1lo;
            c1[t][2] = b1hi; c1[t][3] = b1hi;
        }
        #pragma unroll 2
        for (int s = 0; s < 25; s++) {
            const float* wb = W1s + (s * 8 + qa) * WST + m0 + ra;
            uint32_t a0 = __float_as_uint(wb[0]);
            uint32_t a1 = __float_as_uint(wb[8]);
            uint32_t a2 = __float_as_uint(wb[4 * WST]);
            uint32_t a3 = __float_as_uint(wb[4 * WST + 8]);
            const float* bb = B1 + (s * 8 + qa) * BST + ra;
            #pragma unroll
            for (int t = 0; t < 8; t++) {
                uint32_t bb0 = __float_as_uint(bb[t * 8]);
                uint32_t bb1 = __float_as_uint(bb[4 * BST + t * 8]);
                mma8(c1[t], a0, a1, a2, a3, bb0, bb1);
            }
        }
        __syncthreads();   // all B1 reads done before H overwrites it

        // ---- SiLU -> H[k=m][n], tf32-rounded (H aliases B1) ----
        #pragma unroll
        for (int t = 0; t < 8; t++) {
            int n = t * 8 + qa * 2;
            float2 lo = make_float2(__uint_as_float(tf32u(silu(c1[t][0]))),
                                    __uint_as_float(tf32u(silu(c1[t][1]))));
            float2 hi = make_float2(__uint_as_float(tf32u(silu(c1[t][2]))),
                                    __uint_as_float(tf32u(silu(c1[t][3]))));
            *(float2*)(B1 + (m0 + ra) * BST + n)     = lo;
            *(float2*)(B1 + (m0 + ra + 8) * BST + n) = hi;
        }
        __syncthreads();

        // ---- layer 2: D2 = W2^T x H, K=128 (16 k-steps) ----
        float c2[8][4];
        #pragma unroll
        for (int t = 0; t < 8; t++) {
            c2[t][0] = b2lo; c2[t][1] = b2lo;
            c2[t][2] = b2hi; c2[t][3] = b2hi;
        }
        #pragma unroll 2
        for (int s = 0; s < 16; s++) {
            const float* wb = W2s + (s * 8 + qa) * WST + m0 + ra;
            uint32_t a0 = __float_as_uint(wb[0]);
            uint32_t a1 = __float_as_uint(wb[8]);
            uint32_t a2 = __float_as_uint(wb[4 * WST]);
            uint32_t a3 = __float_as_uint(wb[4 * WST + 8]);
            const float* bb = B1 + (s * 8 + qa) * BST + ra;
            #pragma unroll
            for (int t = 0; t < 8; t++) {
                uint32_t bb0 = __float_as_uint(bb[t * 8]);
                uint32_t bb1 = __float_as_uint(bb[4 * BST + t * 8]);
                mma8(c2[t], a0, a1, a2, a3, bb0, bb1);
            }
        }

        // ---- scatter-add: row m -> out[dst*64 + m] (s-half or v-half) ----
        #pragma unroll
        for (int t = 0; t < 8; t++) {
            int n = t * 8 + qa * 2;
            int d0 = dstS[n];
            int d1 = dstS[n + 1];
            red_add_f(obase + (size_t)d0 * 64 + rlo,     c2[t][0]);
            red_add_f(obase + (size_t)d1 * 64 + rlo,     c2[t][1]);
            red_add_f(obase + (size_t)d0 * 64 + rlo + 8, c2[t][2]);
            red_add_f(obase + (size_t)d1 * 64 + rlo + 8, c2[t][3]);
        }
    }
}

extern "C" void kernel_launch(void* const* d_in, const int* in_sizes, int n_in,
                              void* d_out, int out_size) {
    const float* h_s    = (const float*)d_in[0];
    const float* h_v    = (const float*)d_in[1];
    const float* pos    = (const float*)d_in[2];
    const float* orient = (const float*)d_in[3];
    const float* W1     = (const float*)d_in[4];
    const float* b1     = (const float*)d_in[5];
    const float* W2     = (const float*)d_in[6];
    const float* b2     = (const float*)d_in[7];
    const int*   ei     = (const int*)d_in[8];
    float* out = (float*)d_out;

    (void)in_sizes; (void)n_in; (void)out_size;

    int n4 = NN * SD / 4;
    init_out_kernel<<<(n4 + 255) / 256, 256>>>(h_s, h_v, out);

    cudaFuncSetAttribute(edge_kernel,
                         cudaFuncAttributeMaxDynamicSharedMemorySize, SMEM_BYTES);
    int nsm = 148;
    cudaDeviceGetAttribute(&nsm, cudaDevAttrMultiProcessorCount, 0);
    edge_kernel<<<nsm, NTHREADS, SMEM_BYTES>>>(h_s, h_v, pos, orient,
                                               W1, b1, W2, b2, ei, out);
}

// round 14
// speedup vs baseline: 2.2701x; 1.2072x over previous
#include <cuda_runtime.h>
#include <math.h>
#include <stdint.h>

#define NN 100000
#define NE 1600000
#define SD 64
#define VD 64
#define HID 128
#define TILE 64
#define NT (NE / TILE)            // 25000 exact
#define NTHREADS 256

// SMEM layout (floats)
//  W2f : per-warp fragment-order W2: 8 warps x 16 ksteps x 32 chunks x 4 = 16384 floats
//  B1f : frag-order messages: 25 ksteps x 512 = 12800 floats  (staging [64][132] aliases)
//  Hf  : frag-order hidden:   16 ksteps x 512 = 8192 floats
//  dstS: 64 ints
#define W2F_OFF 0
#define B1F_OFF 16384
#define HF_OFF  (B1F_OFF + 12800)          // 29184
#define DST_OFF (HF_OFF + 8192)            // 37376
#define SMEM_FLOATS (DST_OFF + 64)
#define SMEM_BYTES  (SMEM_FLOATS * 4)      // ~149.8 KB

__device__ __forceinline__ uint32_t tf32u(float x) {
    uint32_t u;
    asm("cvt.rna.tf32.f32 %0, %1;" : "=r"(u) : "f"(x));
    return u;
}
__device__ __forceinline__ float uaf(uint32_t u) { return __uint_as_float(u); }

__device__ __forceinline__ void mma8(float c[4], uint32_t a0, uint32_t a1,
                                     uint32_t a2, uint32_t a3,
                                     uint32_t b0, uint32_t b1) {
    asm volatile("mma.sync.aligned.m16n8k8.row.col.f32.tf32.tf32.f32 "
        "{%0,%1,%2,%3}, {%4,%5,%6,%7}, {%8,%9}, {%0,%1,%2,%3};"
        : "+f"(c[0]), "+f"(c[1]), "+f"(c[2]), "+f"(c[3])
        : "r"(a0), "r"(a1), "r"(a2), "r"(a3), "r"(b0), "r"(b1));
}

__device__ __forceinline__ void red_add_v4(float* a, float x, float y, float z, float w) {
    asm volatile("red.global.add.v4.f32 [%0], {%1,%2,%3,%4};"
                 :: "l"(a), "f"(x), "f"(y), "f"(z), "f"(w) : "memory");
}

__device__ __forceinline__ float silu(float x) {
    return x * (1.f / (1.f + __expf(-x)));
}

// B1 frag index: value (k, e) -> float offset within B1f
//   s=k>>3, q=k&3, half=(k>>2)&1, ra=e&7, t=e>>3
//   c = half*2 + (t>>2), chunk = q*8 + ra, j = t&3
__device__ __forceinline__ int b1idx(int e, int k) {
    int s = k >> 3, q = k & 3, half = (k >> 2) & 1;
    int ra = e & 7, t = e >> 3;
    return s * 512 + (half * 2 + (t >> 2)) * 128 + (q * 8 + ra) * 4 + (t & 3);
}

__global__ void init_out_kernel(const float* __restrict__ hs,
                                const float* __restrict__ hv,
                                float* __restrict__ out) {
    size_t i = (size_t)blockIdx.x * blockDim.x + threadIdx.x;
    const size_t n4 = (size_t)NN * SD / 4;
    if (i < n4) {
        ((float4*)out)[i]      = ((const float4*)hs)[i];
        ((float4*)out)[n4 + i] = ((const float4*)hv)[i];
    }
}

extern __shared__ float sm[];

__global__ void __launch_bounds__(NTHREADS, 1)
edge_kernel(const float* __restrict__ h_s, const float* __restrict__ h_v,
            const float* __restrict__ pos, const float* __restrict__ orient,
            const float* __restrict__ W1,  const float* __restrict__ gb1,
            const float* __restrict__ W2,  const float* __restrict__ gb2,
            const int*   __restrict__ ei,  float* __restrict__ out) {
    float* W2f = sm + W2F_OFF;
    float* B1f = sm + B1F_OFF;
    float* Hf  = sm + HF_OFF;
    float* stage = B1f;                       // [64][132], aliases B1f
    int*  dstS = (int*)(sm + DST_OFF);

    const int tid  = threadIdx.x;
    const int wid  = tid >> 5;
    const int lane = tid & 31;
    const int qa   = lane & 3;
    const int ra   = lane >> 2;
    const int m0   = wid * 16;

    // ---- W2 -> per-warp fragment-order SMEM (once) ----
    for (int i = tid; i < 16384; i += NTHREADS) {
        int wd = i >> 11, rem = i & 2047;
        int s = rem >> 7, rem2 = rem & 127;
        int ch = rem2 >> 2, j = rem2 & 3;
        int qq = ch >> 3, rr = ch & 7;
        int k = s * 8 + qq + (j >> 1) * 4;
        int m = wd * 16 + rr + (j & 1) * 8;
        W2f[i] = uaf(tf32u(W2[(size_t)k * HID + m]));
    }

    // ---- W1 A-fragments -> registers (100 regs, once) ----
    uint32_t w1a[25][4];
    #pragma unroll
    for (int s = 0; s < 25; s++) {
        int k0 = s * 8 + qa, k1 = k0 + 4;
        w1a[s][0] = (k0 < 195) ? tf32u(W1[(size_t)k0 * HID + m0 + ra])     : 0u;
        w1a[s][1] = (k0 < 195) ? tf32u(W1[(size_t)k0 * HID + m0 + ra + 8]) : 0u;
        w1a[s][2] = (k1 < 195) ? tf32u(W1[(size_t)k1 * HID + m0 + ra])     : 0u;
        w1a[s][3] = (k1 < 195) ? tf32u(W1[(size_t)k1 * HID + m0 + ra + 8]) : 0u;
    }

    const float b1lo = gb1[m0 + ra], b1hi = gb1[m0 + ra + 8];
    const float b2lo = gb2[m0 + ra], b2hi = gb2[m0 + ra + 8];

    const int e = tid & 63;                    // builder edge
    const int p = tid >> 6;                    // builder role (warp-uniform)
    const size_t outv_off = (size_t)NN * SD;
    const int ch4  = (qa * 8 + ra) * 4;        // straight chunk (B1, W2f)
    const int ch4x = (qa * 8 + (ra ^ qa)) * 4; // xor-swizzled chunk (Hf)

    // epilogue-2 reader coords
    const int er = tid >> 2, part = tid & 3;
    float* rbase = (part < 2) ? out + part * 32 : out + outv_off + (part - 2) * 32;

    // H-store constants
    const int s2lo = m0 >> 3, s2hi = s2lo + 1;
    const int q2 = ra & 3, h2 = (ra >> 2) & 1;
    const int chA = (q2 * 8 + ((qa * 2) ^ q2)) * 4;       // delta = 0
    const int chB = (q2 * 8 + (((qa * 2) | 1) ^ q2)) * 4; // delta = 1

    __syncthreads();   // W2f visible

    for (int tile = blockIdx.x; tile < NT; tile += gridDim.x) {
        __syncthreads();   // stage/dstS consumed; B1f free

        // ---- builder: B1f[k][e] frag-order, tf32, conflict-free stores ----
        {
            int ge = tile * TILE + e;
            int src = ei[ge];
            int dst = ei[NE + ge];
            if (p == 0) {                      // k 0..63 : h_s[src]
                const float4* r = (const float4*)(h_s + (size_t)src * SD);
                #pragma unroll
                for (int j4 = 0; j4 < 16; j4++) {
                    float4 v = r[j4];
                    B1f[b1idx(e, 4*j4+0)] = uaf(tf32u(v.x));
                    B1f[b1idx(e, 4*j4+1)] = uaf(tf32u(v.y));
                    B1f[b1idx(e, 4*j4+2)] = uaf(tf32u(v.z));
                    B1f[b1idx(e, 4*j4+3)] = uaf(tf32u(v.w));
                }
            } else if (p == 1) {               // k 64..127 : h_s[dst]
                const float4* r = (const float4*)(h_s + (size_t)dst * SD);
                #pragma unroll
                for (int j4 = 0; j4 < 16; j4++) {
                    float4 v = r[j4];
                    B1f[b1idx(e, 64+4*j4+0)] = uaf(tf32u(v.x));
                    B1f[b1idx(e, 64+4*j4+1)] = uaf(tf32u(v.y));
                    B1f[b1idx(e, 64+4*j4+2)] = uaf(tf32u(v.z));
                    B1f[b1idx(e, 64+4*j4+3)] = uaf(tf32u(v.w));
                }
            } else if (p == 2) {               // k 128..191 : rotated h_v[src]
                float alpha = orient[dst];
                float beta  = orient[src];
                float c, s_;
                sincosf(2.f * (beta - alpha), &s_, &c);
                const float4* r = (const float4*)(h_v + (size_t)src * VD);
                #pragma unroll
                for (int j4 = 0; j4 < 16; j4++) {
                    float4 v = r[j4];
                    B1f[b1idx(e, 128+4*j4+0)] = uaf(tf32u(v.x * c - v.y * s_));
                    B1f[b1idx(e, 128+4*j4+1)] = uaf(tf32u(v.x * s_ + v.y * c));
                    B1f[b1idx(e, 128+4*j4+2)] = uaf(tf32u(v.z * c - v.w * s_));
                    B1f[b1idx(e, 128+4*j4+3)] = uaf(tf32u(v.z * s_ + v.w * c));
                }
            } else {                           // k 192..199 : geo + zero pad
                float2 ps = ((const float2*)pos)[src];
                float2 pd = ((const float2*)pos)[dst];
                float dx = ps.x - pd.x, dy = ps.y - pd.y;
                float dist = sqrtf(dx * dx + dy * dy) + 1e-6f;
                float alpha = orient[dst];
                float dphi = atan2f(dy, dx) - alpha;
                float c2g, s2g;
                sincosf(2.f * dphi, &s2g, &c2g);
                B1f[b1idx(e, 192)] = uaf(tf32u(dist));
                B1f[b1idx(e, 193)] = uaf(tf32u(c2g));
                B1f[b1idx(e, 194)] = uaf(tf32u(s2g));
                B1f[b1idx(e, 195)] = 0.f;
                B1f[b1idx(e, 196)] = 0.f;
                B1f[b1idx(e, 197)] = 0.f;
                B1f[b1idx(e, 198)] = 0.f;
                B1f[b1idx(e, 199)] = 0.f;
                dstS[e] = dst;
            }
        }
        __syncthreads();

        // ---- layer 1: W1(regs) x B1f(4x LDS.128/kstep), 25 ksteps ----
        float c1[8][4];
        #pragma unroll
        for (int t = 0; t < 8; t++) {
            c1[t][0] = b1lo; c1[t][1] = b1lo;
            c1[t][2] = b1hi; c1[t][3] = b1hi;
        }
        #pragma unroll
        for (int s = 0; s < 25; s++) {
            const float* bb = B1f + s * 512 + ch4;
            float4 v0 = *(const float4*)(bb);         // b0 tiles 0..3
            float4 v1 = *(const float4*)(bb + 128);   // b0 tiles 4..7
            float4 v2 = *(const float4*)(bb + 256);   // b1 tiles 0..3
            float4 v3 = *(const float4*)(bb + 384);   // b1 tiles 4..7
            uint32_t a0 = w1a[s][0], a1 = w1a[s][1], a2 = w1a[s][2], a3 = w1a[s][3];
            mma8(c1[0], a0,a1,a2,a3, __float_as_uint(v0.x), __float_as_uint(v2.x));
            mma8(c1[1], a0,a1,a2,a3, __float_as_uint(v0.y), __float_as_uint(v2.y));
            mma8(c1[2], a0,a1,a2,a3, __float_as_uint(v0.z), __float_as_uint(v2.z));
            mma8(c1[3], a0,a1,a2,a3, __float_as_uint(v0.w), __float_as_uint(v2.w));
            mma8(c1[4], a0,a1,a2,a3, __float_as_uint(v1.x), __float_as_uint(v3.x));
            mma8(c1[5], a0,a1,a2,a3, __float_as_uint(v1.y), __float_as_uint(v3.y));
            mma8(c1[6], a0,a1,a2,a3, __float_as_uint(v1.z), __float_as_uint(v3.z));
            mma8(c1[7], a0,a1,a2,a3, __float_as_uint(v1.w), __float_as_uint(v3.w));
        }

        // ---- epilogue 1: SiLU -> Hf (frag-order, xor chunk; <=2-way stores) ----
        #pragma unroll
        for (int t = 0; t < 8; t++) {
            int bt = (t >> 1) * 128 + (t & 1) * 2 + h2;
            Hf[s2lo * 512 + bt + chA] = uaf(tf32u(silu(c1[t][0])));
            Hf[s2lo * 512 + bt + chB] = uaf(tf32u(silu(c1[t][1])));
            Hf[s2hi * 512 + bt + chA] = uaf(tf32u(silu(c1[t][2])));
            Hf[s2hi * 512 + bt + chB] = uaf(tf32u(silu(c1[t][3])));
        }
        __syncthreads();

        // ---- layer 2: W2f(1x LDS.128) x Hf(4x LDS.128), 16 ksteps ----
        float c2[8][4];
        #pragma unroll
        for (int t = 0; t < 8; t++) {
            c2[t][0] = b2lo; c2[t][1] = b2lo;
            c2[t][2] = b2hi; c2[t][3] = b2hi;
        }
        #pragma unroll
        for (int s = 0; s < 16; s++) {
            float4 wa = *(const float4*)(W2f + wid * 2048 + s * 128 + ch4);
            uint32_t a0 = __float_as_uint(wa.x), a1 = __float_as_uint(wa.y);
            uint32_t a2 = __float_as_uint(wa.z), a3 = __float_as_uint(wa.w);
            const float* hb = Hf + s * 512 + ch4x;
            float4 v0 = *(const float4*)(hb);         // tiles 0,1 (b0,b1 pairs)
            float4 v1 = *(const float4*)(hb + 128);   // tiles 2,3
            float4 v2 = *(const float4*)(hb + 256);   // tiles 4,5
            float4 v3 = *(const float4*)(hb + 384);   // tiles 6,7
            mma8(c2[0], a0,a1,a2,a3, __float_as_uint(v0.x), __float_as_uint(v0.y));
            mma8(c2[1], a0,a1,a2,a3, __float_as_uint(v0.z), __float_as_uint(v0.w));
            mma8(c2[2], a0,a1,a2,a3, __float_as_uint(v1.x), __float_as_uint(v1.y));
            mma8(c2[3], a0,a1,a2,a3, __float_as_uint(v1.z), __float_as_uint(v1.w));
            mma8(c2[4], a0,a1,a2,a3, __float_as_uint(v2.x), __float_as_uint(v2.y));
            mma8(c2[5], a0,a1,a2,a3, __float_as_uint(v2.z), __float_as_uint(v2.w));
            mma8(c2[6], a0,a1,a2,a3, __float_as_uint(v3.x), __float_as_uint(v3.y));
            mma8(c2[7], a0,a1,a2,a3, __float_as_uint(v3.z), __float_as_uint(v3.w));
        }

        // ---- stage D2 as [e][m] (conflict-free scalar stores) ----
        #pragma unroll
        for (int t = 0; t < 8; t++) {
            int n = t * 8 + qa * 2;
            stage[n * 132 + m0 + ra]           = c2[t][0];
            stage[(n + 1) * 132 + m0 + ra]     = c2[t][1];
            stage[n * 132 + m0 + ra + 8]       = c2[t][2];
            stage[(n + 1) * 132 + m0 + ra + 8] = c2[t][3];
        }
        __syncthreads();

        // ---- vector scatter: 8x LDS.128 + 8x red.v4 per thread ----
        {
            int d = dstS[er];
            const float4* row = (const float4*)(stage + er * 132 + part * 32);
            float* basep = rbase + (size_t)d * 64;
            #pragma unroll
            for (int c4 = 0; c4 < 8; c4++) {
                float4 v = row[c4];
                red_add_v4(basep + c4 * 4, v.x, v.y, v.z, v.w);
            }
        }
    }
}

extern "C" void kernel_launch(void* const* d_in, const int* in_sizes, int n_in,
                              void* d_out, int out_size) {
    const float* h_s    = (const float*)d_in[0];
    const float* h_v    = (const float*)d_in[1];
    const float* pos    = (const float*)d_in[2];
    const float* orient = (const float*)d_in[3];
    const float* W1     = (const float*)d_in[4];
    const float* b1     = (const float*)d_in[5];
    const float* W2     = (const float*)d_in[6];
    const float* b2     = (const float*)d_in[7];
    const int*   ei     = (const int*)d_in[8];
    float* out = (float*)d_out;

    (void)in_sizes; (void)n_in; (void)out_size;

    int n4 = NN * SD / 4;
    init_out_kernel<<<(n4 + 255) / 256, 256>>>(h_s, h_v, out);

    cudaFuncSetAttribute(edge_kernel,
                         cudaFuncAttributeMaxDynamicSharedMemorySize, SMEM_BYTES);
    int nsm = 148;
    cudaDeviceGetAttribute(&nsm, cudaDevAttrMultiProcessorCount, 0);
    edge_kernel<<<nsm, NTHREADS, SMEM_BYTES>>>(h_s, h_v, pos, orient,
                                               W1, b1, W2, b2, ei, out);
}

// round 15
// speedup vs baseline: 2.4780x; 1.0916x over previous
#include <cuda_runtime.h>
#include <math.h>
#include <stdint.h>

#define NN 100000
#define NE 1600000
#define SD 64
#define VD 64
#define HID 128
#define TILE 64
#define NT (NE / TILE)            // 25000 exact
#define NTHREADS 384              // 8 compute warps + 4 builder warps

// SMEM layout (floats)
#define W2F_OFF 0                 // 16384 (frag-order W2, per-warp slices)
#define B1F_OFF 16384             // 2 x 12800 (double-buffered frag-order messages)
#define HS_OFF  (B1F_OFF + 2*12800)   // 41984: H (16x512=8192) UNION stage (64x132=8448)
#define DST_OFF (HS_OFF + 8448)       // 50432: 2 x 64 ints
#define SMEM_FLOATS (DST_OFF + 128)
#define SMEM_BYTES  (SMEM_FLOATS * 4) // ~202.2 KB

__device__ __forceinline__ uint32_t tf32u(float x) {
    uint32_t u;
    asm("cvt.rna.tf32.f32 %0, %1;" : "=r"(u) : "f"(x));
    return u;
}
__device__ __forceinline__ float uaf(uint32_t u) { return __uint_as_float(u); }

__device__ __forceinline__ void mma8(float c[4], uint32_t a0, uint32_t a1,
                                     uint32_t a2, uint32_t a3,
                                     uint32_t b0, uint32_t b1) {
    asm volatile("mma.sync.aligned.m16n8k8.row.col.f32.tf32.tf32.f32 "
        "{%0,%1,%2,%3}, {%4,%5,%6,%7}, {%8,%9}, {%0,%1,%2,%3};"
        : "+f"(c[0]), "+f"(c[1]), "+f"(c[2]), "+f"(c[3])
        : "r"(a0), "r"(a1), "r"(a2), "r"(a3), "r"(b0), "r"(b1));
}

__device__ __forceinline__ void red_add_v4(float* a, float x, float y, float z, float w) {
    asm volatile("red.global.add.v4.f32 [%0], {%1,%2,%3,%4};"
                 :: "l"(a), "f"(x), "f"(y), "f"(z), "f"(w) : "memory");
}

__device__ __forceinline__ float silu(float x) {
    return x * (1.f / (1.f + __expf(-x)));
}

#define BAR_SYNC(id, cnt)   asm volatile("bar.sync %0, %1;"   :: "r"(id), "r"(cnt) : "memory")
#define BAR_ARRIVE(id, cnt) asm volatile("bar.arrive %0, %1;" :: "r"(id), "r"(cnt) : "memory")

// B1 frag index: value (k, e) -> float offset within one B1 buffer
__device__ __forceinline__ int b1idx(int e, int k) {
    int s = k >> 3, q = k & 3, half = (k >> 2) & 1;
    int ra = e & 7, t = e >> 3;
    return s * 512 + (half * 2 + (t >> 2)) * 128 + (q * 8 + ra) * 4 + (t & 3);
}

__global__ void init_out_kernel(const float* __restrict__ hs,
                                const float* __restrict__ hv,
                                float* __restrict__ out) {
    size_t i = (size_t)blockIdx.x * blockDim.x + threadIdx.x;
    const size_t n4 = (size_t)NN * SD / 4;
    if (i < n4) {
        ((float4*)out)[i]      = ((const float4*)hs)[i];
        ((float4*)out)[n4 + i] = ((const float4*)hv)[i];
    }
}

extern __shared__ float sm[];

__global__ void __launch_bounds__(NTHREADS, 1)
edge_kernel(const float* __restrict__ h_s, const float* __restrict__ h_v,
            const float* __restrict__ pos, const float* __restrict__ orient,
            const float* __restrict__ W1,  const float* __restrict__ gb1,
            const float* __restrict__ W2,  const float* __restrict__ gb2,
            const int*   __restrict__ ei,  float* __restrict__ out) {
    float* W2f = sm + W2F_OFF;
    float* HS  = sm + HS_OFF;                 // H frag buffer, aliased by stage[64][132]
    int*  dstS = (int*)(sm + DST_OFF);        // [2][64]

    const int tid  = threadIdx.x;
    const int wid  = tid >> 5;
    const int lane = tid & 31;

    // ---- W2 -> frag-order SMEM (all 384 threads) ----
    for (int i = tid; i < 16384; i += NTHREADS) {
        int wd = i >> 11, rem = i & 2047;
        int s = rem >> 7, rem2 = rem & 127;
        int ch = rem2 >> 2, j = rem2 & 3;
        int qq = ch >> 3, rr = ch & 7;
        int k = s * 8 + qq + (j >> 1) * 4;
        int m = wd * 16 + rr + (j & 1) * 8;
        W2f[i] = uaf(tf32u(W2[(size_t)k * HID + m]));
    }
    __syncthreads();

    if (wid < 8) {
        // ================= COMPUTE WARPS =================
        const int qa = lane & 3;
        const int ra = lane >> 2;
        const int m0 = wid * 16;

        // W1 A-fragments -> registers
        uint32_t w1a[25][4];
        #pragma unroll
        for (int s = 0; s < 25; s++) {
            int k0 = s * 8 + qa, k1 = k0 + 4;
            w1a[s][0] = (k0 < 195) ? tf32u(W1[(size_t)k0 * HID + m0 + ra])     : 0u;
            w1a[s][1] = (k0 < 195) ? tf32u(W1[(size_t)k0 * HID + m0 + ra + 8]) : 0u;
            w1a[s][2] = (k1 < 195) ? tf32u(W1[(size_t)k1 * HID + m0 + ra])     : 0u;
            w1a[s][3] = (k1 < 195) ? tf32u(W1[(size_t)k1 * HID + m0 + ra + 8]) : 0u;
        }
        const float b1lo = gb1[m0 + ra], b1hi = gb1[m0 + ra + 8];
        const float b2lo = gb2[m0 + ra], b2hi = gb2[m0 + ra + 8];

        const size_t outv_off = (size_t)NN * SD;
        const int ch4  = (qa * 8 + ra) * 4;
        const int ch4x = (qa * 8 + (ra ^ qa)) * 4;
        const int er = tid >> 2, part = tid & 3;
        float* rbase = (part < 2) ? out + part * 32 : out + outv_off + (part - 2) * 32;
        const int s2lo = m0 >> 3, s2hi = s2lo + 1;
        const int q2 = ra & 3, h2 = (ra >> 2) & 1;
        const int chA = (q2 * 8 + ((qa * 2) ^ q2)) * 4;
        const int chB = (q2 * 8 + (((qa * 2) | 1) ^ q2)) * 4;
        float* stage = HS;                    // [64][132]

        int seq = 0;
        for (int tile = blockIdx.x; tile < NT; tile += gridDim.x, seq++) {
            const int b = seq & 1;
            const float* B1f = sm + B1F_OFF + b * 12800;

            BAR_SYNC(1 + b, 384);             // B1[b], dstS[b] full
            int dreg = dstS[b * 64 + er];     // grab dst before freeing

            // ---- layer 1: W1(regs) x B1f ----
            float c1[8][4];
            #pragma unroll
            for (int t = 0; t < 8; t++) {
                c1[t][0] = b1lo; c1[t][1] = b1lo;
                c1[t][2] = b1hi; c1[t][3] = b1hi;
            }
            #pragma unroll
            for (int s = 0; s < 25; s++) {
                const float* bb = B1f + s * 512 + ch4;
                float4 v0 = *(const float4*)(bb);
                float4 v1 = *(const float4*)(bb + 128);
                float4 v2 = *(const float4*)(bb + 256);
                float4 v3 = *(const float4*)(bb + 384);
                uint32_t a0 = w1a[s][0], a1 = w1a[s][1], a2 = w1a[s][2], a3 = w1a[s][3];
                mma8(c1[0], a0,a1,a2,a3, __float_as_uint(v0.x), __float_as_uint(v2.x));
                mma8(c1[1], a0,a1,a2,a3, __float_as_uint(v0.y), __float_as_uint(v2.y));
                mma8(c1[2], a0,a1,a2,a3, __float_as_uint(v0.z), __float_as_uint(v2.z));
                mma8(c1[3], a0,a1,a2,a3, __float_as_uint(v0.w), __float_as_uint(v2.w));
                mma8(c1[4], a0,a1,a2,a3, __float_as_uint(v1.x), __float_as_uint(v3.x));
                mma8(c1[5], a0,a1,a2,a3, __float_as_uint(v1.y), __float_as_uint(v3.y));
                mma8(c1[6], a0,a1,a2,a3, __float_as_uint(v1.z), __float_as_uint(v3.z));
                mma8(c1[7], a0,a1,a2,a3, __float_as_uint(v1.w), __float_as_uint(v3.w));
            }
            BAR_ARRIVE(3 + b, 384);           // B1[b] free for builders (seq+2)

            BAR_SYNC(5, 256);                 // all compute: prev scatter done + L1 done

            // ---- epilogue 1: SiLU -> H (frag-order) ----
            #pragma unroll
            for (int t = 0; t < 8; t++) {
                int bt = (t >> 1) * 128 + (t & 1) * 2 + h2;
                HS[s2lo * 512 + bt + chA] = uaf(tf32u(silu(c1[t][0])));
                HS[s2lo * 512 + bt + chB] = uaf(tf32u(silu(c1[t][1])));
                HS[s2hi * 512 + bt + chA] = uaf(tf32u(silu(c1[t][2])));
                HS[s2hi * 512 + bt + chB] = uaf(tf32u(silu(c1[t][3])));
            }
            BAR_SYNC(5, 256);                 // H complete

            // ---- layer 2 ----
            float c2[8][4];
            #pragma unroll
            for (int t = 0; t < 8; t++) {
                c2[t][0] = b2lo; c2[t][1] = b2lo;
                c2[t][2] = b2hi; c2[t][3] = b2hi;
            }
            #pragma unroll
            for (int s = 0; s < 16; s++) {
                float4 wa = *(const float4*)(W2f + wid * 2048 + s * 128 + ch4);
                uint32_t a0 = __float_as_uint(wa.x), a1 = __float_as_uint(wa.y);
                uint32_t a2 = __float_as_uint(wa.z), a3 = __float_as_uint(wa.w);
                const float* hb = HS + s * 512 + ch4x;
                float4 v0 = *(const float4*)(hb);
                float4 v1 = *(const float4*)(hb + 128);
                float4 v2 = *(const float4*)(hb + 256);
                float4 v3 = *(const float4*)(hb + 384);
                mma8(c2[0], a0,a1,a2,a3, __float_as_uint(v0.x), __float_as_uint(v0.y));
                mma8(c2[1], a0,a1,a2,a3, __float_as_uint(v0.z), __float_as_uint(v0.w));
                mma8(c2[2], a0,a1,a2,a3, __float_as_uint(v1.x), __float_as_uint(v1.y));
                mma8(c2[3], a0,a1,a2,a3, __float_as_uint(v1.z), __float_as_uint(v1.w));
                mma8(c2[4], a0,a1,a2,a3, __float_as_uint(v2.x), __float_as_uint(v2.y));
                mma8(c2[5], a0,a1,a2,a3, __float_as_uint(v2.z), __float_as_uint(v2.w));
                mma8(c2[6], a0,a1,a2,a3, __float_as_uint(v3.x), __float_as_uint(v3.y));
                mma8(c2[7], a0,a1,a2,a3, __float_as_uint(v3.z), __float_as_uint(v3.w));
            }
            BAR_SYNC(5, 256);                 // all H reads done; stage may overwrite

            // ---- stage D2 as [e][m] ----
            #pragma unroll
            for (int t = 0; t < 8; t++) {
                int n = t * 8 + qa * 2;
                stage[n * 132 + m0 + ra]           = c2[t][0];
                stage[(n + 1) * 132 + m0 + ra]     = c2[t][1];
                stage[n * 132 + m0 + ra + 8]       = c2[t][2];
                stage[(n + 1) * 132 + m0 + ra + 8] = c2[t][3];
            }
            BAR_SYNC(5, 256);                 // stage complete

            // ---- vector scatter ----
            {
                const float4* row = (const float4*)(stage + er * 132 + part * 32);
                float* basep = rbase + (size_t)dreg * 64;
                #pragma unroll
                for (int c4 = 0; c4 < 8; c4++) {
                    float4 v = row[c4];
                    red_add_v4(basep + c4 * 4, v.x, v.y, v.z, v.w);
                }
            }
        }
    } else {
        // ================= BUILDER WARPS (wid 8..11) =================
        const int btid = tid - 256;           // 0..127
        const int e = btid & 63;
        const int p = btid >> 6;              // 0 or 1

        int seq = 0;
        for (int tile = blockIdx.x; tile < NT; tile += gridDim.x, seq++) {
            const int b = seq & 1;
            float* B1f = sm + B1F_OFF + b * 12800;

            if (seq >= 2) BAR_SYNC(3 + b, 384);   // wait buffer freed

            int ge = tile * TILE + e;
            int src = ei[ge];
            int dst = ei[NE + ge];
            float alpha = orient[dst];
            float beta  = orient[src];
            float c, s_;
            sincosf(2.f * (beta - alpha), &s_, &c);

            if (p == 0) {
                // k 0..63 : h_s[src]
                const float4* r = (const float4*)(h_s + (size_t)src * SD);
                #pragma unroll
                for (int j4 = 0; j4 < 16; j4++) {
                    float4 v = r[j4];
                    B1f[b1idx(e, 4*j4+0)] = uaf(tf32u(v.x));
                    B1f[b1idx(e, 4*j4+1)] = uaf(tf32u(v.y));
                    B1f[b1idx(e, 4*j4+2)] = uaf(tf32u(v.z));
                    B1f[b1idx(e, 4*j4+3)] = uaf(tf32u(v.w));
                }
                // k 128..159 : rotated h_v[src], first half
                const float4* rv = (const float4*)(h_v + (size_t)src * VD);
                #pragma unroll
                for (int j4 = 0; j4 < 8; j4++) {
                    float4 v = rv[j4];
                    B1f[b1idx(e, 128+4*j4+0)] = uaf(tf32u(v.x * c - v.y * s_));
                    B1f[b1idx(e, 128+4*j4+1)] = uaf(tf32u(v.x * s_ + v.y * c));
                    B1f[b1idx(e, 128+4*j4+2)] = uaf(tf32u(v.z * c - v.w * s_));
                    B1f[b1idx(e, 128+4*j4+3)] = uaf(tf32u(v.z * s_ + v.w * c));
                }
            } else {
                // k 64..127 : h_s[dst]
                const float4* r = (const float4*)(h_s + (size_t)dst * SD);
                #pragma unroll
                for (int j4 = 0; j4 < 16; j4++) {
                    float4 v = r[j4];
                    B1f[b1idx(e, 64+4*j4+0)] = uaf(tf32u(v.x));
                    B1f[b1idx(e, 64+4*j4+1)] = uaf(tf32u(v.y));
                    B1f[b1idx(e, 64+4*j4+2)] = uaf(tf32u(v.z));
                    B1f[b1idx(e, 64+4*j4+3)] = uaf(tf32u(v.w));
                }
                // k 160..191 : rotated h_v[src], second half
                const float4* rv = (const float4*)(h_v + (size_t)src * VD);
                #pragma unroll
                for (int j4 = 8; j4 < 16; j4++) {
                    float4 v = rv[j4];
                    B1f[b1idx(e, 128+4*j4+0)] = uaf(tf32u(v.x * c - v.y * s_));
                    B1f[b1idx(e, 128+4*j4+1)] = uaf(tf32u(v.x * s_ + v.y * c));
                    B1f[b1idx(e, 128+4*j4+2)] = uaf(tf32u(v.z * c - v.w * s_));
                    B1f[b1idx(e, 128+4*j4+3)] = uaf(tf32u(v.z * s_ + v.w * c));
                }
                // k 192..199 : geo + zero pad
                float2 ps = ((const float2*)pos)[src];
                float2 pd = ((const float2*)pos)[dst];
                float dx = ps.x - pd.x, dy = ps.y - pd.y;
                float dist = sqrtf(dx * dx + dy * dy) + 1e-6f;
                float dphi = atan2f(dy, dx) - alpha;
                float c2g, s2g;
                sincosf(2.f * dphi, &s2g, &c2g);
                B1f[b1idx(e, 192)] = uaf(tf32u(dist));
                B1f[b1idx(e, 193)] = uaf(tf32u(c2g));
                B1f[b1idx(e, 194)] = uaf(tf32u(s2g));
                B1f[b1idx(e, 195)] = 0.f;
                B1f[b1idx(e, 196)] = 0.f;
                B1f[b1idx(e, 197)] = 0.f;
                B1f[b1idx(e, 198)] = 0.f;
                B1f[b1idx(e, 199)] = 0.f;
                dstS[b * 64 + e] = dst;
            }
            BAR_ARRIVE(1 + b, 384);           // B1[b] full
        }
    }
}

extern "C" void kernel_launch(void* const* d_in, const int* in_sizes, int n_in,
                              void* d_out, int out_size) {
    const float* h_s    = (const float*)d_in[0];
    const float* h_v    = (const float*)d_in[1];
    const float* pos    = (const float*)d_in[2];
    const float* orient = (const float*)d_in[3];
    const float* W1     = (const float*)d_in[4];
    const float* b1     = (const float*)d_in[5];
    const float* W2     = (const float*)d_in[6];
    const float* b2     = (const float*)d_in[7];
    const int*   ei     = (const int*)d_in[8];
    float* out = (float*)d_out;

    (void)in_sizes; (void)n_in; (void)out_size;

    int n4 = NN * SD / 4;
    init_out_kernel<<<(n4 + 255) / 256, 256>>>(h_s, h_v, out);

    cudaFuncSetAttribute(edge_kernel,
                         cudaFuncAttributeMaxDynamicSharedMemorySize, SMEM_BYTES);
    int nsm = 148;
    cudaDeviceGetAttribute(&nsm, cudaDevAttrMultiProcessorCount, 0);
    edge_kernel<<<nsm, NTHREADS, SMEM_BYTES>>>(h_s, h_v, pos, orient,
                                               W1, b1, W2, b2, ei, out);
}

// round 17
// speedup vs baseline: 3.0412x; 1.2273x over previous
#include <cuda_runtime.h>
#include <math.h>
#include <stdint.h>

#define NN 100000
#define NE 1600000
#define SD 64
#define VD 64
#define HID 128
#define TILE 64
#define NT (NE / TILE)            // 25000 exact
#define NTHREADS 384              // 8 compute warps + 4 builder warps
#define PAD 204                   // B row stride (floats): mod32=12 -> conflict-free frag reads

// SMEM layout (floats)
#define W2F_OFF 0                 // 16384 (frag-order W2, per-warp slices)
#define B_OFF   16384             // 2 x 13056 (double-buffered row-major B [64][204])
#define BUFSZ   (TILE * PAD)      // 13056
#define HS_OFF  (B_OFF + 2 * BUFSZ)    // 42496: H (8192) UNION stage (64x132=8448)
#define DST_OFF (HS_OFF + 8448)        // 50944: 2 x 64 ints
#define SRC_OFF (DST_OFF + 128)        // 2 x 64 ints
#define CS_OFF  (SRC_OFF + 128)        // 2 x 64 floats
#define SS_OFF  (CS_OFF + 128)         // 2 x 64 floats
#define SMEM_FLOATS (SS_OFF + 128)
#define SMEM_BYTES  (SMEM_FLOATS * 4)  // ~205.5 KB

__device__ __forceinline__ uint32_t tf32u(float x) {
    uint32_t u;
    asm("cvt.rna.tf32.f32 %0, %1;" : "=r"(u) : "f"(x));
    return u;
}
__device__ __forceinline__ float uaf(uint32_t u) { return __uint_as_float(u); }

__device__ __forceinline__ void mma8(float c[4], uint32_t a0, uint32_t a1,
                                     uint32_t a2, uint32_t a3,
                                     uint32_t b0, uint32_t b1) {
    asm volatile("mma.sync.aligned.m16n8k8.row.col.f32.tf32.tf32.f32 "
        "{%0,%1,%2,%3}, {%4,%5,%6,%7}, {%8,%9}, {%0,%1,%2,%3};"
        : "+f"(c[0]), "+f"(c[1]), "+f"(c[2]), "+f"(c[3])
        : "r"(a0), "r"(a1), "r"(a2), "r"(a3), "r"(b0), "r"(b1));
}

__device__ __forceinline__ void red_add_v4(float* a, float x, float y, float z, float w) {
    asm volatile("red.global.add.v4.f32 [%0], {%1,%2,%3,%4};"
                 :: "l"(a), "f"(x), "f"(y), "f"(z), "f"(w) : "memory");
}

__device__ __forceinline__ float silu(float x) {
    return x * (1.f / (1.f + __expf(-x)));
}

#define BAR_SYNC(id, cnt)   asm volatile("bar.sync %0, %1;"   :: "r"(id), "r"(cnt) : "memory")
#define BAR_ARRIVE(id, cnt) asm volatile("bar.arrive %0, %1;" :: "r"(id), "r"(cnt) : "memory")

__global__ void init_out_kernel(const float* __restrict__ hs,
                                const float* __restrict__ hv,
                                float* __restrict__ out) {
    size_t i = (size_t)blockIdx.x * blockDim.x + threadIdx.x;
    const size_t n4 = (size_t)NN * SD / 4;
    if (i < n4) {
        ((float4*)out)[i]      = ((const float4*)hs)[i];
        ((float4*)out)[n4 + i] = ((const float4*)hv)[i];
    }
}

extern __shared__ float sm[];

__global__ void __launch_bounds__(NTHREADS, 1)
edge_kernel(const float* __restrict__ h_s, const float* __restrict__ h_v,
            const float* __restrict__ pos, const float* __restrict__ orient,
            const float* __restrict__ W1,  const float* __restrict__ gb1,
            const float* __restrict__ W2,  const float* __restrict__ gb2,
            const int*   __restrict__ ei,  float* __restrict__ out) {
    float* W2f = sm + W2F_OFF;
    float* HS  = sm + HS_OFF;                 // H frag buffer, aliased by stage[64][132]
    int*  dstS = (int*)(sm + DST_OFF);        // [2][64]
    int*  srcS = (int*)(sm + SRC_OFF);        // [2][64]  (double-buffered: fixes R16 race)
    float* cS  = sm + CS_OFF;                 // [2][64]
    float* sS  = sm + SS_OFF;                 // [2][64]

    const int tid  = threadIdx.x;
    const int wid  = tid >> 5;
    const int lane = tid & 31;

    // ---- W2 -> frag-order SMEM (all 384 threads) ----
    for (int i = tid; i < 16384; i += NTHREADS) {
        int wd = i >> 11, rem = i & 2047;
        int s = rem >> 7, rem2 = rem & 127;
        int ch = rem2 >> 2, j = rem2 & 3;
        int qq = ch >> 3, rr = ch & 7;
        int k = s * 8 + qq + (j >> 1) * 4;
        int m = wd * 16 + rr + (j & 1) * 8;
        W2f[i] = uaf(tf32u(W2[(size_t)k * HID + m]));
    }
    __syncthreads();

    if (wid < 8) {
        // ================= COMPUTE WARPS =================
        const int qa = lane & 3;
        const int ra = lane >> 2;
        const int m0 = wid * 16;

        // W1 A-fragments -> registers
        uint32_t w1a[25][4];
        #pragma unroll
        for (int s = 0; s < 25; s++) {
            int k0 = s * 8 + qa, k1 = k0 + 4;
            w1a[s][0] = (k0 < 195) ? tf32u(W1[(size_t)k0 * HID + m0 + ra])     : 0u;
            w1a[s][1] = (k0 < 195) ? tf32u(W1[(size_t)k0 * HID + m0 + ra + 8]) : 0u;
            w1a[s][2] = (k1 < 195) ? tf32u(W1[(size_t)k1 * HID + m0 + ra])     : 0u;
            w1a[s][3] = (k1 < 195) ? tf32u(W1[(size_t)k1 * HID + m0 + ra + 8]) : 0u;
        }
        const float b1lo = gb1[m0 + ra], b1hi = gb1[m0 + ra + 8];
        const float b2lo = gb2[m0 + ra], b2hi = gb2[m0 + ra + 8];

        const size_t outv_off = (size_t)NN * SD;
        const int ch4  = (qa * 8 + ra) * 4;
        const int ch4x = (qa * 8 + (ra ^ qa)) * 4;
        const int er = tid >> 2, part = tid & 3;
        float* rbase = (part < 2) ? out + part * 32 : out + outv_off + (part - 2) * 32;
        const int s2lo = m0 >> 3, s2hi = s2lo + 1;
        const int q2 = ra & 3, h2 = (ra >> 2) & 1;
        const int chA = (q2 * 8 + ((qa * 2) ^ q2)) * 4;
        const int chB = (q2 * 8 + (((qa * 2) | 1) ^ q2)) * 4;
        float* stage = HS;                    // [64][132], col-swizzled m'=(m+8n)&127

        int seq = 0;
        for (int tile = blockIdx.x; tile < NT; tile += gridDim.x, seq++) {
            const int b = seq & 1;
            const float* Bb = sm + B_OFF + b * BUFSZ;
            const float* bp = Bb + ra * PAD + qa;   // row-major frag base

            BAR_SYNC(1 + b, 384);             // B[b], dstS[b] full
            int dreg = dstS[b * 64 + er];     // grab dst before freeing

            // ---- layer 1: W1(regs) x B(row-major, 16x LDS.32/kstep) ----
            float c1[8][4];
            #pragma unroll
            for (int t = 0; t < 8; t++) {
                c1[t][0] = b1lo; c1[t][1] = b1lo;
                c1[t][2] = b1hi; c1[t][3] = b1hi;
            }
            #pragma unroll
            for (int s = 0; s < 25; s++) {
                const float* bs = bp + s * 8;
                uint32_t a0 = w1a[s][0], a1 = w1a[s][1], a2 = w1a[s][2], a3 = w1a[s][3];
                #pragma unroll
                for (int t = 0; t < 8; t++) {
                    uint32_t bb0 = __float_as_uint(bs[t * (8 * PAD)]);
                    uint32_t bb1 = __float_as_uint(bs[t * (8 * PAD) + 4]);
                    mma8(c1[t], a0, a1, a2, a3, bb0, bb1);
                }
            }
            BAR_ARRIVE(3 + b, 384);           // B[b] free for builders (seq+2)

            BAR_SYNC(5, 256);                 // all compute: prev scatter done + L1 done

            // ---- epilogue 1: SiLU -> H (frag-order) ----
            #pragma unroll
            for (int t = 0; t < 8; t++) {
                int bt = (t >> 1) * 128 + (t & 1) * 2 + h2;
                HS[s2lo * 512 + bt + chA] = uaf(tf32u(silu(c1[t][0])));
                HS[s2lo * 512 + bt + chB] = uaf(tf32u(silu(c1[t][1])));
                HS[s2hi * 512 + bt + chA] = uaf(tf32u(silu(c1[t][2])));
                HS[s2hi * 512 + bt + chB] = uaf(tf32u(silu(c1[t][3])));
            }
            BAR_SYNC(5, 256);                 // H complete

            // ---- layer 2 ----
            float c2[8][4];
            #pragma unroll
            for (int t = 0; t < 8; t++) {
                c2[t][0] = b2lo; c2[t][1] = b2lo;
                c2[t][2] = b2hi; c2[t][3] = b2hi;
            }
            #pragma unroll
            for (int s = 0; s < 16; s++) {
                float4 wa = *(const float4*)(W2f + wid * 2048 + s * 128 + ch4);
                uint32_t a0 = __float_as_uint(wa.x), a1 = __float_as_uint(wa.y);
                uint32_t a2 = __float_as_uint(wa.z), a3 = __float_as_uint(wa.w);
                const float* hb = HS + s * 512 + ch4x;
                float4 v0 = *(const float4*)(hb);
                float4 v1 = *(const float4*)(hb + 128);
                float4 v2 = *(const float4*)(hb + 256);
                float4 v3 = *(const float4*)(hb + 384);
                mma8(c2[0], a0,a1,a2,a3, __float_as_uint(v0.x), __float_as_uint(v0.y));
                mma8(c2[1], a0,a1,a2,a3, __float_as_uint(v0.z), __float_as_uint(v0.w));
                mma8(c2[2], a0,a1,a2,a3, __float_as_uint(v1.x), __float_as_uint(v1.y));
                mma8(c2[3], a0,a1,a2,a3, __float_as_uint(v1.z), __float_as_uint(v1.w));
                mma8(c2[4], a0,a1,a2,a3, __float_as_uint(v2.x), __float_as_uint(v2.y));
                mma8(c2[5], a0,a1,a2,a3, __float_as_uint(v2.z), __float_as_uint(v2.w));
                mma8(c2[6], a0,a1,a2,a3, __float_as_uint(v3.x), __float_as_uint(v3.y));
                mma8(c2[7], a0,a1,a2,a3, __float_as_uint(v3.z), __float_as_uint(v3.w));
            }
            BAR_SYNC(5, 256);                 // all H reads done; stage may overwrite

            // ---- stage D2 as [e][m'] with m' = (m + 8n) & 127 ----
            #pragma unroll
            for (int t = 0; t < 8; t++) {
                int n0 = t * 8 + qa * 2, n1 = n0 + 1;
                stage[n0 * 132 + ((m0 + ra     + 8 * n0) & 127)] = c2[t][0];
                stage[n1 * 132 + ((m0 + ra     + 8 * n1) & 127)] = c2[t][1];
                stage[n0 * 132 + ((m0 + ra + 8 + 8 * n0) & 127)] = c2[t][2];
                stage[n1 * 132 + ((m0 + ra + 8 + 8 * n1) & 127)] = c2[t][3];
            }
            BAR_SYNC(5, 256);                 // stage complete

            // ---- vector scatter (conflict-free swizzled reads) ----
            {
                float* basep = rbase + (size_t)dreg * 64;
                #pragma unroll
                for (int c4 = 0; c4 < 8; c4++) {
                    int msw = (part * 32 + c4 * 4 + 8 * er) & 127;
                    float4 v = *(const float4*)(stage + er * 132 + msw);
                    red_add_v4(basep + c4 * 4, v.x, v.y, v.z, v.w);
                }
            }
        }
    } else {
        // ================= BUILDER WARPS (wid 8..11) =================
        const int btid  = tid - 256;          // 0..127
        const int bwarp = btid >> 5;          // 0..3
        const int half  = (btid >> 4) & 1;    // which row of the pair
        const int jj    = btid & 15;          // 16B chunk within row

        int seq = 0;
        for (int tile = blockIdx.x; tile < NT; tile += gridDim.x, seq++) {
            const int b = seq & 1;
            float* Bb = sm + B_OFF + b * BUFSZ;

            if (seq >= 2) BAR_SYNC(3 + b, 384);   // wait buffer freed

            // ---- phase A: per-edge scalars (threads 0..63), aux slot b ----
            if (btid < 64) {
                const int e = btid;
                int ge = tile * TILE + e;
                int src = ei[ge];
                int dst = ei[NE + ge];
                srcS[b * 64 + e] = src;
                dstS[b * 64 + e] = dst;
                float alpha = orient[dst];
                float beta  = orient[src];
                float c, s_;
                sincosf(2.f * (beta - alpha), &s_, &c);
                cS[b * 64 + e] = c; sS[b * 64 + e] = s_;
                float2 ps = ((const float2*)pos)[src];
                float2 pd = ((const float2*)pos)[dst];
                float dx = ps.x - pd.x, dy = ps.y - pd.y;
                float dist = sqrtf(dx * dx + dy * dy) + 1e-6f;
                float dphi = atan2f(dy, dx) - alpha;
                float c2g, s2g;
                sincosf(2.f * dphi, &s2g, &c2g);
                *(float4*)(Bb + e * PAD + 192) =
                    make_float4(uaf(tf32u(dist)), uaf(tf32u(c2g)), uaf(tf32u(s2g)), 0.f);
                *(float4*)(Bb + e * PAD + 196) = make_float4(0.f, 0.f, 0.f, 0.f);
            }
            BAR_SYNC(6, 128);                 // aux[b] ready for phase B

            // ---- phase B: coalesced row gather (192 rows, 2 rows/warp-instr) ----
            #pragma unroll 4
            for (int i = 0; i < 24; i++) {
                int r   = bwarp * 48 + 2 * i + half;
                int typ = r >> 6;             // 0: hs[src], 1: hs[dst], 2: hv[src]
                int er  = r & 63;
                int node = (typ == 1) ? dstS[b * 64 + er] : srcS[b * 64 + er];
                const float* gb = (typ == 2) ? h_v : h_s;
                float4 v = ((const float4*)(gb + (size_t)node * 64))[jj];
                if (typ == 2) {
                    float c = cS[b * 64 + er], s_ = sS[b * 64 + er];
                    v = make_float4(v.x * c - v.y * s_, v.x * s_ + v.y * c,
                                    v.z * c - v.w * s_, v.z * s_ + v.w * c);
                }
                uint4 u;
                u.x = tf32u(v.x); u.y = tf32u(v.y);
                u.z = tf32u(v.z); u.w = tf32u(v.w);
                *(uint4*)(Bb + er * PAD + (typ << 6) + 4 * jj) = u;
            }
            BAR_ARRIVE(1 + b, 384);           // B[b] full
        }
    }
}

extern "C" void kernel_launch(void* const* d_in, const int* in_sizes, int n_in,
                              void* d_out, int out_size) {
    const float* h_s    = (const float*)d_in[0];
    const float* h_v    = (const float*)d_in[1];
    const float* pos    = (const float*)d_in[2];
    const float* orient = (const float*)d_in[3];
    const float* W1     = (const float*)d_in[4];
    const float* b1     = (const float*)d_in[5];
    const float* W2     = (const float*)d_in[6];
    const float* b2     = (const float*)d_in[7];
    const int*   ei     = (const int*)d_in[8];
    float* out = (float*)d_out;

    (void)in_sizes; (void)n_in; (void)out_size;

    int n4 = NN * SD / 4;
    init_out_kernel<<<(n4 + 255) / 256, 256>>>(h_s, h_v, out);

    cudaFuncSetAttribute(edge_kernel,
                         cudaFuncAttributeMaxDynamicSharedMemorySize, SMEM_BYTES);
    int nsm = 148;
    cudaDeviceGetAttribute(&nsm, cudaDevAttrMultiProcessorCount, 0);
    edge_kernel<<<nsm, NTHREADS, SMEM_BYTES>>>(h_s, h_v, pos, orient,
                                               W1, b1, W2, b2, ei, out);
}